// round 13
// baseline (speedup 1.0000x reference)
#include <cuda_runtime.h>
#include <cuda_bf16.h>
#include <cuda_fp16.h>
#include <math.h>

#define NN 50000
#define EE 800000
#define DD 96
#define HIDN 128
#define OUTD 8
#define BN_EPS 1e-5f
#define AGG_EPS 1e-6f
#define NTILE 6250

// ---------------- device scratch ----------------
__device__ __align__(16) float g_h[NN * DD];
__device__ __align__(16) float g_A[NN * DD];
__device__ __align__(16) __half g_BDh[NN * DD * 2];  // B at [0,96), D at [96,192) per node
__device__ __align__(16) __half g_Eh[NN * DD];
__device__ __align__(16) float g_agg[NN * DD * 2];   // interleaved num/den
__device__ __align__(16) float g_hnew[NN * DD];
__device__ __align__(16) __half g_e[EE * DD];        // sorted order
__device__ __align__(16) __half g_enew[EE * DD];     // sorted order
__device__ __align__(16) float g_sums[4 * DD];
__device__ __align__(16) float g_scale_e[DD], g_shift_e[DD];
__device__ __align__(16) float g_scale_h[DD], g_shift_h[DD];
__device__ __align__(16) __half g_Wf_hi[20 * DD * DD];
__device__ __align__(16) __half g_Wf_lo[20 * DD * DD];
// dst-sorted edge structure
__device__ int g_perm[EE];
__device__ int g_src_s[EE];
__device__ int g_dst_s[EE];
__device__ int g_off[NN];
__device__ int g_cursor[NN];

// ---------------- helpers ----------------
__device__ __forceinline__ unsigned pack_h2(float x, float y) {
    __half2 t = __floats2half2_rn(x, y);
    return *reinterpret_cast<unsigned*>(&t);
}

__device__ __forceinline__ float sigmoid_fast(float x) {
    float t;
    asm("tanh.approx.f32 %0, %1;" : "=f"(t) : "f"(0.5f * x));
    return fmaf(0.5f, t, 0.5f);
}

__device__ __forceinline__ void prefetchL2(const void* p) {
    asm volatile("prefetch.global.L2 [%0];" :: "l"(p));
}

__device__ __forceinline__ void mma_f16(float* c, const unsigned* a, unsigned b0, unsigned b1) {
    asm volatile(
        "mma.sync.aligned.m16n8k16.row.col.f32.f16.f16.f32 "
        "{%0,%1,%2,%3},{%4,%5,%6,%7},{%8,%9},{%0,%1,%2,%3};"
        : "+f"(c[0]), "+f"(c[1]), "+f"(c[2]), "+f"(c[3])
        : "r"(a[0]), "r"(a[1]), "r"(a[2]), "r"(a[3]), "r"(b0), "r"(b1));
}

// ---------------- fused: dst histogram + weight prep ----------------
struct WPtrs { const float *a, *b, *c, *d, *e; };

__global__ void k_histprep(const int* __restrict__ dst, WPtrs p) {
    int idx = blockIdx.x * blockDim.x + threadIdx.x;
    if (idx < EE) atomicAdd(&g_off[dst[idx]], 1);
    if (idx < 20 * DD * DD) {
        int m = idx / (DD * DD), r = idx % (DD * DD);
        int k = r / DD, n = r % DD;
        int type = m >> 2, layer = m & 3;
        const float* src = type == 0 ? p.a : type == 1 ? p.b : type == 2 ? p.c
                           : type == 3 ? p.d : p.e;
        float w = src[layer * DD * DD + k * DD + n];
        __half hi = __float2half(w);
        g_Wf_hi[m * DD * DD + n * DD + k] = hi;
        g_Wf_lo[m * DD * DD + n * DD + k] = __float2half(w - __half2float(hi));
    }
}

__global__ void k_scan() {
    __shared__ int ssum[1024];
    const int STRIP = (NN + 1023) / 1024;
    int t = threadIdx.x;
    int beg = t * STRIP, end = beg + STRIP;
    if (end > NN) end = NN;
    int s = 0;
    for (int i = beg; i < end; i++) s += g_off[i];
    ssum[t] = s;
    __syncthreads();
    for (int ofs = 1; ofs < 1024; ofs <<= 1) {
        int v = (t >= ofs) ? ssum[t - ofs] : 0;
        __syncthreads();
        ssum[t] += v;
        __syncthreads();
    }
    int carry = (t > 0) ? ssum[t - 1] : 0;
    for (int i = beg; i < end; i++) {
        int v = g_off[i];
        g_off[i] = carry;
        carry += v;
    }
}

// smem layout node (u32): Ah[128*50] Whi[96*52] Wlo[96*52]
#define N_A 0
#define N_WHI (128 * 50)
#define N_WLO (128 * 50 + 96 * 52)
#define NODE_U32 (128 * 50 + 2 * 96 * 52)   // 16384 u32 = 65536 B

// ---------------- fused node GEMM (+ scatter when fuse==2) ----------------
__global__ __launch_bounds__(256, 3) void k_node(const float* __restrict__ bA, const float* __restrict__ bB,
                                                 const float* __restrict__ bD, const float* __restrict__ bE,
                                                 int layer, int fuse,
                                                 const float* __restrict__ h1, const float* __restrict__ h2,
                                                 const float* __restrict__ z,
                                                 const float* __restrict__ Wh_emb,
                                                 const float* __restrict__ bh_emb,
                                                 const int* __restrict__ src_in,
                                                 const int* __restrict__ dst_in) {
    extern __shared__ unsigned sm[];
    unsigned* Ah = sm + N_A;
    unsigned* Whi = sm + N_WHI;
    unsigned* Wlo = sm + N_WLO;
    int tid = threadIdx.x;

    if (fuse == 2) {
        int e = blockIdx.x * 256 + tid;
        if (e < EE) {
            int d = dst_in[e];
            int p = g_off[d] + atomicAdd(&g_cursor[d], 1);
            g_perm[p] = e;
            g_src_s[p] = src_in[e];
            g_dst_s[p] = d;
        }
        if (blockIdx.x >= (NN + 127) / 128) return;
    }

    int m0 = blockIdx.x * 128;
    int rows_valid = NN - m0;
    if (rows_valid > 128) rows_valid = 128;

    if (fuse == 2) {
        float* Whf = (float*)(sm + N_WHI);
        for (int i = tid; i < 26 * 96; i += 256) Whf[i] = Wh_emb[i];
        __syncthreads();
        for (int i = tid; i < 128 * 24; i += 256) {
            int r = i / 24, c4 = i % 24;
            int row = m0 + r;
            float4 v = make_float4(0.f, 0.f, 0.f, 0.f);
            if (r < rows_valid) {
                float x[26];
                const float* p1 = h1 + row * 6;
#pragma unroll
                for (int k = 0; k < 6; k++) x[k] = p1[k];
                const float* p2 = h2 + row * 4;
#pragma unroll
                for (int k = 0; k < 4; k++) x[6 + k] = p2[k];
                const float* p3 = z + row * 16;
#pragma unroll
                for (int k = 0; k < 16; k++) x[10 + k] = p3[k];
                float a[4];
#pragma unroll
                for (int c = 0; c < 4; c++) a[c] = bh_emb[c4 * 4 + c];
#pragma unroll
                for (int k = 0; k < 26; k++) {
#pragma unroll
                    for (int c = 0; c < 4; c++)
                        a[c] = fmaf(x[k], Whf[k * 96 + c4 * 4 + c], a[c]);
                }
                v = make_float4(a[0], a[1], a[2], a[3]);
                ((float4*)g_h)[(long long)row * 24 + c4] = v;
            }
            Ah[r * 50 + c4 * 2] = pack_h2(v.x, v.y);
            Ah[r * 50 + c4 * 2 + 1] = pack_h2(v.z, v.w);
        }
    } else {
        for (int i = tid; i < 128 * 24; i += 256) {
            int r = i / 24, c4 = i % 24;
            float4 v = make_float4(0.f, 0.f, 0.f, 0.f);
            if (r < rows_valid) {
                long long gi = (long long)(m0 + r) * 24 + c4;
                v = ((const float4*)g_h)[gi];
                float4 en = ((const float4*)g_hnew)[gi];
                int c = c4 * 4;
                v.x += fmaxf(0.f, en.x * g_scale_h[c] + g_shift_h[c]);
                v.y += fmaxf(0.f, en.y * g_scale_h[c + 1] + g_shift_h[c + 1]);
                v.z += fmaxf(0.f, en.z * g_scale_h[c + 2] + g_shift_h[c + 2]);
                v.w += fmaxf(0.f, en.w * g_scale_h[c + 3] + g_shift_h[c + 3]);
                ((float4*)g_h)[gi] = v;
            }
            Ah[r * 50 + c4 * 2] = pack_h2(v.x, v.y);
            Ah[r * 50 + c4 * 2 + 1] = pack_h2(v.z, v.w);
        }
    }

    int w = tid >> 5, lane = tid & 31;
    int wm = w & 3, wn = w >> 2;
    const int types[4] = {0, 1, 3, 4};
    const float* biases[4] = {bA, bB, bD, bE};

    for (int t = 0; t < 4; t++) {
        __syncthreads();
        const unsigned* gwh = (const unsigned*)(g_Wf_hi + (types[t] * 4 + layer) * DD * DD);
        const unsigned* gwl = (const unsigned*)(g_Wf_lo + (types[t] * 4 + layer) * DD * DD);
        for (int i = tid; i < 96 * 48; i += 256) {
            int n = i / 48, kp = i % 48;
            Whi[n * 52 + kp] = gwh[i];
            Wlo[n * 52 + kp] = gwl[i];
        }
        __syncthreads();

        float acc[2][6][4];
#pragma unroll
        for (int m = 0; m < 2; m++)
#pragma unroll
            for (int n = 0; n < 6; n++)
#pragma unroll
                for (int j = 0; j < 4; j++) acc[m][n][j] = 0.f;

#pragma unroll
        for (int kt = 0; kt < 6; kt++) {
            int kp = kt * 8 + (lane & 3);
            unsigned ah[2][4];
#pragma unroll
            for (int m = 0; m < 2; m++) {
                int row = wm * 32 + m * 16 + (lane >> 2);
                ah[m][0] = Ah[row * 50 + kp];
                ah[m][1] = Ah[(row + 8) * 50 + kp];
                ah[m][2] = Ah[row * 50 + kp + 4];
                ah[m][3] = Ah[(row + 8) * 50 + kp + 4];
            }
#pragma unroll
            for (int n = 0; n < 6; n++) {
                int col = wn * 48 + n * 8 + (lane >> 2);
                unsigned bh0 = Whi[col * 52 + kp], bh1 = Whi[col * 52 + kp + 4];
                unsigned bl0 = Wlo[col * 52 + kp], bl1 = Wlo[col * 52 + kp + 4];
#pragma unroll
                for (int m = 0; m < 2; m++) {
                    mma_f16(acc[m][n], ah[m], bh0, bh1);
                    mma_f16(acc[m][n], ah[m], bl0, bl1);
                }
            }
        }

        const float* bias = biases[t];
#pragma unroll
        for (int m = 0; m < 2; m++) {
#pragma unroll
            for (int n = 0; n < 6; n++) {
                int row = m0 + wm * 32 + m * 16 + (lane >> 2);
                int col = wn * 48 + n * 8 + ((lane & 3) << 1);
                float b0 = bias[col], b1 = bias[col + 1];
                float v00 = acc[m][n][0] + b0, v01 = acc[m][n][1] + b1;
                float v10 = acc[m][n][2] + b0, v11 = acc[m][n][3] + b1;
                if (t == 0) {
                    if (row < NN)
                        *(float2*)&g_A[(long long)row * 96 + col] = make_float2(v00, v01);
                    if (row + 8 < NN)
                        *(float2*)&g_A[(long long)(row + 8) * 96 + col] = make_float2(v10, v11);
                } else if (t < 3) {
                    int ofs = (t == 1) ? 0 : 96;
                    if (row < NN)
                        *(__half2*)&g_BDh[(long long)row * 192 + ofs + col] = __floats2half2_rn(v00, v01);
                    if (row + 8 < NN)
                        *(__half2*)&g_BDh[(long long)(row + 8) * 192 + ofs + col] = __floats2half2_rn(v10, v11);
                } else {
                    if (row < NN)
                        *(__half2*)&g_Eh[(long long)row * 96 + col] = __floats2half2_rn(v00, v01);
                    if (row + 8 < NN)
                        *(__half2*)&g_Eh[(long long)(row + 8) * 96 + col] = __floats2half2_rn(v10, v11);
                }
            }
        }
    }
}

// smem layout edge (u32): Whi[96*52] Wemb[384] | Ah/Sst[128*50] Sbv[128*50] Sde[128*50]
#define EW_HI 0
#define EW_EMB (96 * 52)
#define ER_OFF (96 * 52 + 384)
#define ESBV_OFF (ER_OFF + 6400)
#define ESDE_OFF (ER_OFF + 12800)
#define EDGE_U32 (ER_OFF + 19200)   // 24576 u32 = 98304 B

// ---------------- persistent fused edge layer (384 threads, smem-staged D+E) ----------------
__global__ __launch_bounds__(384, 2) void k_edge(const __half* __restrict__ Whi_g,
                                                 const float* __restrict__ bC,
                                                 const float* __restrict__ efeat,
                                                 const float* __restrict__ We,
                                                 const float* __restrict__ be,
                                                 int fuse, int last) {
    extern __shared__ unsigned sm[];
    unsigned* Whi = sm + EW_HI;
    float* Wemb = (float*)(sm + EW_EMB);
    unsigned* Ah = sm + ER_OFF;              // aliases Sst
    __half* Sst = (__half*)(sm + ER_OFF);    // 128x100 halves (vv)
    __half* Sbv = (__half*)(sm + ESBV_OFF);  // 128x100 halves (B rows)
    unsigned* SbvU = sm + ESBV_OFF;
    __half* Sde = (__half*)(sm + ESDE_OFF);  // 128x100 halves (D[src]+E[dst])
    unsigned* SdeU = sm + ESDE_OFF;
    __shared__ int s_src[128], s_dst[128];
    int tid = threadIdx.x;

    {
        const unsigned* gwh = (const unsigned*)Whi_g;
        for (int i = tid; i < 96 * 48; i += 384) {
            int n = i / 48, kp = i % 48;
            Whi[n * 52 + kp] = gwh[i];
        }
        if (fuse == 0 && tid < 384) Wemb[tid] = We[tid];
    }

    int w = tid >> 5, lane = tid & 31;
    int wm = w & 3, wn = w >> 2;              // 4 x 3 warp grid
    int rP = tid / 3, thirdP = tid % 3;       // gather-stage split
    int colPair = (tid % 48) * 2, gP2 = tid / 48;  // pass-2: 8 groups x 16 rows
    float bs0 = 0.f, bs1 = 0.f, bq0 = 0.f, bq1 = 0.f;

    float bcr[8];
#pragma unroll
    for (int n = 0; n < 4; n++) {
        int col = wn * 32 + n * 8 + ((lane & 3) << 1);
        bcr[2 * n] = bC[col];
        bcr[2 * n + 1] = bC[col + 1];
    }

    for (int tile = blockIdx.x; tile < NTILE; tile += gridDim.x) {
        int e0 = tile * 128;
        __syncthreads();
        if (tid < 128) {
            s_src[tid] = g_src_s[e0 + tid];
            s_dst[tid] = g_dst_s[e0 + tid];
        }

        // gather stage: B raw + (D[src]+E[dst]) into smem; latency hidden by GEMM
        {
            int s = g_src_s[e0 + rP];
            int d = g_dst_s[e0 + rP];
            const uint4* Br = (const uint4*)(g_BDh + (long long)s * 192) + thirdP * 4;
            const uint4* Dr = (const uint4*)(g_BDh + (long long)s * 192) + 12 + thirdP * 4;
            const uint4* Er = (const uint4*)(g_Eh + (long long)d * 96) + thirdP * 4;
            unsigned* pb = SbvU + rP * 50 + thirdP * 16;
            unsigned* pd = SdeU + rP * 50 + thirdP * 16;
#pragma unroll
            for (int i = 0; i < 4; i++) {
                uint4 bu = Br[i];
                pb[i * 4] = bu.x; pb[i * 4 + 1] = bu.y;
                pb[i * 4 + 2] = bu.z; pb[i * 4 + 3] = bu.w;
            }
#pragma unroll
            for (int i = 0; i < 4; i++) {
                uint4 du = Dr[i], eu = Er[i];
                __half2* dh = (__half2*)&du;
                __half2* eh = (__half2*)&eu;
                __half2 s0 = __hadd2(dh[0], eh[0]);
                __half2 s1 = __hadd2(dh[1], eh[1]);
                __half2 s2 = __hadd2(dh[2], eh[2]);
                __half2 s3 = __hadd2(dh[3], eh[3]);
                pd[i * 4] = *(unsigned*)&s0;
                pd[i * 4 + 1] = *(unsigned*)&s1;
                pd[i * 4 + 2] = *(unsigned*)&s2;
                pd[i * 4 + 3] = *(unsigned*)&s3;
            }
        }

        if (fuse == 0) {
            for (int i = tid; i < 128 * 12; i += 384) {
                int r = i / 12, c8 = i % 12;
                int er = e0 + r;
                const float4 ef = ((const float4*)efeat)[g_perm[er]];
                uint4 v;
                __half2* vh = (__half2*)&v;
#pragma unroll
                for (int j = 0; j < 4; j++) {
                    int c = c8 * 8 + 2 * j;
                    float o0 = be[c] + ef.x * Wemb[c] + ef.y * Wemb[96 + c] +
                               ef.z * Wemb[192 + c] + ef.w * Wemb[288 + c];
                    float o1 = be[c + 1] + ef.x * Wemb[c + 1] + ef.y * Wemb[96 + c + 1] +
                               ef.z * Wemb[192 + c + 1] + ef.w * Wemb[288 + c + 1];
                    vh[j] = __floats2half2_rn(o0, o1);
                }
                __stcs((uint4*)g_e + (long long)er * 12 + c8, v);
                unsigned* vu = (unsigned*)&v;
#pragma unroll
                for (int j = 0; j < 4; j++) Ah[r * 50 + c8 * 4 + j] = vu[j];
            }
        } else {
            for (int i = tid; i < 128 * 12; i += 384) {
                int r = i / 12, c8 = i % 12;
                long long gi = (long long)(e0 + r) * 12 + c8;
                uint4 v = __ldcs((const uint4*)g_e + gi);
                uint4 en = __ldcs((const uint4*)g_enew + gi);
                __half2* vh = (__half2*)&v;
                __half2* eh = (__half2*)&en;
                int c = c8 * 8;
#pragma unroll
                for (int j = 0; j < 4; j++) {
                    float2 f = __half22float2(vh[j]);
                    float2 ev = __half22float2(eh[j]);
                    f.x += fmaxf(0.f, ev.x * g_scale_e[c + 2 * j] + g_shift_e[c + 2 * j]);
                    f.y += fmaxf(0.f, ev.y * g_scale_e[c + 2 * j + 1] + g_shift_e[c + 2 * j + 1]);
                    vh[j] = __floats2half2_rn(f.x, f.y);
                }
                if (!last) __stcs((uint4*)g_e + gi, v);
                unsigned* vu = (unsigned*)&v;
#pragma unroll
                for (int j = 0; j < 4; j++) Ah[r * 50 + c8 * 4 + j] = vu[j];
            }
        }

        // L2 prefetch for tile + gridDim
        {
            int nt = tile + gridDim.x;
            if (nt < NTILE) {
                int ne0 = nt * 128;
                if (fuse != 0) {
                    const char* eb = (const char*)(g_e + (long long)ne0 * 96);
                    const char* nb = (const char*)(g_enew + (long long)ne0 * 96);
                    const char* p = (tid < 192) ? eb + tid * 128 : nb + (tid - 192) * 128;
                    prefetchL2(p);
                }
                if (tid < 128) {
                    int s = g_src_s[ne0 + tid], d = g_dst_s[ne0 + tid];
                    const char* pb = (const char*)(g_BDh + (long long)s * 192);
                    const char* pe = (const char*)(g_Eh + (long long)d * 96);
                    prefetchL2(pb); prefetchL2(pb + 128); prefetchL2(pb + 256);
                    prefetchL2(pe); prefetchL2(pe + 184);
                }
            }
        }
        __syncthreads();

        // fp16 GEMM: Ce = e @ Whi
        float acc[2][4][4];
#pragma unroll
        for (int m = 0; m < 2; m++)
#pragma unroll
            for (int n = 0; n < 4; n++)
#pragma unroll
                for (int j = 0; j < 4; j++) acc[m][n][j] = 0.f;

#pragma unroll
        for (int kt = 0; kt < 6; kt++) {
            int kp = kt * 8 + (lane & 3);
            unsigned ah[2][4];
#pragma unroll
            for (int m = 0; m < 2; m++) {
                int row = wm * 32 + m * 16 + (lane >> 2);
                ah[m][0] = Ah[row * 50 + kp];
                ah[m][1] = Ah[(row + 8) * 50 + kp];
                ah[m][2] = Ah[row * 50 + kp + 4];
                ah[m][3] = Ah[(row + 8) * 50 + kp + 4];
            }
#pragma unroll
            for (int n = 0; n < 4; n++) {
                int col = wn * 32 + n * 8 + (lane >> 2);
                unsigned bh0 = Whi[col * 52 + kp], bh1 = Whi[col * 52 + kp + 4];
#pragma unroll
                for (int m = 0; m < 2; m++)
                    mma_f16(acc[m][n], ah[m], bh0, bh1);
            }
        }
        __syncthreads();  // all warps done reading Ah

        // fused epilogue: vv = acc + bC + Sde; write Sst + e_new (pure smem + streaming store)
#pragma unroll
        for (int m = 0; m < 2; m++) {
            int lr0 = wm * 32 + m * 16 + (lane >> 2);
            int lr1 = lr0 + 8;
#pragma unroll
            for (int n = 0; n < 4; n++) {
                int col = wn * 32 + n * 8 + ((lane & 3) << 1);
                float2 de0 = __half22float2(*(const __half2*)&Sde[lr0 * 100 + col]);
                float2 de1 = __half22float2(*(const __half2*)&Sde[lr1 * 100 + col]);
                float v00 = acc[m][n][0] + bcr[2 * n] + de0.x;
                float v01 = acc[m][n][1] + bcr[2 * n + 1] + de0.y;
                float v10 = acc[m][n][2] + bcr[2 * n] + de1.x;
                float v11 = acc[m][n][3] + bcr[2 * n + 1] + de1.y;
                __half2 o0 = __floats2half2_rn(v00, v01);
                __half2 o1 = __floats2half2_rn(v10, v11);
                *(__half2*)&Sst[lr0 * 100 + col] = o0;
                *(__half2*)&Sst[lr1 * 100 + col] = o1;
                if (!last) {
                    __stcs((__half2*)&g_enew[(long long)(e0 + lr0) * 96 + col], o0);
                    __stcs((__half2*)&g_enew[(long long)(e0 + lr1) * 96 + col], o1);
                }
            }
        }
        __syncthreads();

        // pass 2: per-column-pair segment scan, 8 groups x 16 rows
        {
            int rbeg = gP2 * 16, rend = rbeg + 16;
            float n0 = 0.f, n1 = 0.f, de0 = 0.f, de1 = 0.f;
            int d = s_dst[rbeg];
            for (int r = rbeg; r < rend; r++) {
                float2 vv = __half22float2(*(const __half2*)&Sst[r * 100 + colPair]);
                float2 bv = __half22float2(*(const __half2*)&Sbv[r * 100 + colPair]);
                float sg0 = sigmoid_fast(vv.x);
                float sg1 = sigmoid_fast(vv.y);
                n0 = fmaf(sg0, bv.x, n0);
                n1 = fmaf(sg1, bv.y, n1);
                de0 += sg0;
                de1 += sg1;
                bs0 += vv.x; bs1 += vv.y;
                bq0 = fmaf(vv.x, vv.x, bq0);
                bq1 = fmaf(vv.y, vv.y, bq1);
                int dn = (r + 1 < rend) ? s_dst[r + 1] : -1;
                if (dn != d) {
                    atomicAdd((float4*)&g_agg[((long long)d * 96 + colPair) * 2],
                              make_float4(n0, de0, n1, de1));
                    n0 = 0.f; n1 = 0.f; de0 = 0.f; de1 = 0.f;
                    d = dn;
                }
            }
        }
    }
    if (!last) {
        atomicAdd(&g_sums[colPair], bs0);
        atomicAdd(&g_sums[colPair + 1], bs1);
        atomicAdd(&g_sums[DD + colPair], bq0);
        atomicAdd(&g_sums[DD + colPair + 1], bq1);
    }
}

// ---------------- h_new + BN-h moments + re-zero agg; block 0 also finalizes BN-e ----------------
__global__ __launch_bounds__(384) void k_hnew(int do_e, const float* __restrict__ eg,
                                              const float* __restrict__ eb) {
    __shared__ float ssum[96], ssq[96];
    int tid = threadIdx.x;
    int col = tid % 96, yr = tid / 96;
    if (blockIdx.x == 0 && do_e && tid < 96) {
        float mu = g_sums[tid] * (1.f / EE);
        float var = g_sums[DD + tid] * (1.f / EE) - mu * mu;
        float rstd = rsqrtf(var + BN_EPS);
        float sc = eg[tid] * rstd;
        g_scale_e[tid] = sc;
        g_shift_e[tid] = eb[tid] - mu * sc;
        g_sums[tid] = 0.f;
        g_sums[DD + tid] = 0.f;
    }
    if (tid < 96) { ssum[tid] = 0.f; ssq[tid] = 0.f; }
    __syncthreads();
    float sm = 0.f, sq = 0.f;
    for (int row = blockIdx.x * 4 + yr; row < NN; row += gridDim.x * 4) {
        int i = row * 96 + col;
        float2 nd = ((float2*)g_agg)[i];
        float v = g_A[i] + nd.x / (nd.y + AGG_EPS);
        g_hnew[i] = v;
        ((float2*)g_agg)[i] = make_float2(0.f, 0.f);
        sm += v;
        sq = fmaf(v, v, sq);
    }
    atomicAdd(&ssum[col], sm);
    atomicAdd(&ssq[col], sq);
    __syncthreads();
    if (tid < 96) {
        atomicAdd(&g_sums[2 * DD + tid], ssum[tid]);
        atomicAdd(&g_sums[3 * DD + tid], ssq[tid]);
    }
}

// ---------------- finalize BN-h stats ----------------
__global__ void k_finalize(const float* __restrict__ g, const float* __restrict__ b) {
    int c = threadIdx.x;
    if (c >= 96) return;
    float mu = g_sums[2 * DD + c] * (1.f / NN);
    float var = g_sums[3 * DD + c] * (1.f / NN) - mu * mu;
    float rstd = rsqrtf(var + BN_EPS);
    float sc = g[c] * rstd;
    g_scale_h[c] = sc;
    g_shift_h[c] = b[c] - mu * sc;
    g_sums[2 * DD + c] = 0.f;
    g_sums[3 * DD + c] = 0.f;
}

// ---------------- MLP head (re-zeroes sort scratch for next replay) ----------------
__global__ __launch_bounds__(128) void k_head(const float* __restrict__ W1,
                                              const float* __restrict__ b1,
                                              const float* __restrict__ W2,
                                              const float* __restrict__ b2,
                                              const float* __restrict__ maxa,
                                              float* __restrict__ out) {
    __shared__ float hs[8][96];
    __shared__ float hid[8][HIDN];
    int r0 = blockIdx.x * 8;
    int tid = threadIdx.x;
    int gid = blockIdx.x * 128 + tid;
    if (gid < NN) { g_off[gid] = 0; g_cursor[gid] = 0; }
    for (int i = tid; i < 8 * 96; i += 128) {
        int r = i / 96, c = i % 96;
        int row = r0 + r;
        float v = 0.f;
        if (row < NN) {
            long long gi = (long long)row * 96 + c;
            v = g_h[gi] + fmaxf(0.f, g_hnew[gi] * g_scale_h[c] + g_shift_h[c]);
        }
        hs[r][c] = v;
    }
    __syncthreads();
    float acc[8];
#pragma unroll
    for (int r = 0; r < 8; r++) acc[r] = b1[tid];
#pragma unroll 4
    for (int k = 0; k < 96; k++) {
        float w = W1[k * HIDN + tid];
#pragma unroll
        for (int r = 0; r < 8; r++) acc[r] += hs[r][k] * w;
    }
#pragma unroll
    for (int r = 0; r < 8; r++) hid[r][tid] = fmaxf(acc[r], 0.f);
    __syncthreads();
    if (tid < 64) {
        int r = tid >> 3, c = tid & 7;
        int row = r0 + r;
        if (row < NN) {
            float a = b2[c];
#pragma unroll 8
            for (int k = 0; k < HIDN; k++) a += hid[r][k] * W2[k * OUTD + c];
            out[(long long)row * OUTD + c] = maxa[row] * tanhf(a);
        }
    }
}

// ---------------- launch ----------------
extern "C" void kernel_launch(void* const* d_in, const int* in_sizes, int n_in,
                              void* d_out, int out_size) {
    const float* h1 = (const float*)d_in[0];
    const float* h2 = (const float*)d_in[1];
    const float* z = (const float*)d_in[2];
    const float* efeat = (const float*)d_in[3];
    const float* max_action = (const float*)d_in[4];
    const float* Wh_emb = (const float*)d_in[5];
    const float* bh_emb = (const float*)d_in[6];
    const float* We_emb = (const float*)d_in[7];
    const float* be_emb = (const float*)d_in[8];
    const float* WA = (const float*)d_in[9];
    const float* bA = (const float*)d_in[10];
    const float* WB = (const float*)d_in[11];
    const float* bB = (const float*)d_in[12];
    const float* WC = (const float*)d_in[13];
    const float* bC = (const float*)d_in[14];
    const float* WD = (const float*)d_in[15];
    const float* bD = (const float*)d_in[16];
    const float* WE = (const float*)d_in[17];
    const float* bE = (const float*)d_in[18];
    const float* bn_h_g = (const float*)d_in[19];
    const float* bn_h_b = (const float*)d_in[20];
    const float* bn_e_g = (const float*)d_in[21];
    const float* bn_e_b = (const float*)d_in[22];
    const float* W1 = (const float*)d_in[23];
    const float* b1 = (const float*)d_in[24];
    const float* W2 = (const float*)d_in[25];
    const float* b2 = (const float*)d_in[26];
    const int* src = (const int*)d_in[27];
    const int* dst = (const int*)d_in[28];
    float* out = (float*)d_out;

    __half* p_wfhi;
    cudaGetSymbolAddress((void**)&p_wfhi, g_Wf_hi);

    const int smem_node = NODE_U32 * 4;  // 65536
    const int smem_edge = EDGE_U32 * 4;  // 98304
    cudaFuncSetAttribute(k_node, cudaFuncAttributeMaxDynamicSharedMemorySize, smem_node);
    cudaFuncSetAttribute(k_edge, cudaFuncAttributeMaxDynamicSharedMemorySize, smem_edge);

    WPtrs wp{WA, WB, WC, WD, WE};
    k_histprep<<<(EE + 255) / 256, 256>>>(dst, wp);
    k_scan<<<1, 1024>>>();

    const int nblk = (NN + 127) / 128;  // 391
    const int sblk = (EE + 255) / 256;  // 3125
    const int eblk = 296;

    for (int l = 0; l < 4; l++) {
        k_node<<<(l == 0 ? sblk : nblk), 256, smem_node>>>(
            bA + l * DD, bB + l * DD, bD + l * DD, bE + l * DD,
            l, l == 0 ? 2 : 1, h1, h2, z, Wh_emb, bh_emb, src, dst);
        k_edge<<<eblk, 384, smem_edge>>>(p_wfhi + (2 * 4 + l) * DD * DD,
                                         bC + l * DD, efeat, We_emb, be_emb,
                                         l == 0 ? 0 : 1, l == 3 ? 1 : 0);
        k_hnew<<<256, 384>>>(l < 3 ? 1 : 0, bn_e_g + l * DD, bn_e_b + l * DD);
        k_finalize<<<1, 96>>>(bn_h_g + l * DD, bn_h_b + l * DD);
    }

    k_head<<<NN / 8, 128>>>(W1, b1, W2, b2, max_action, out);
}

// round 15
// speedup vs baseline: 1.1070x; 1.1070x over previous
#include <cuda_runtime.h>
#include <cuda_bf16.h>
#include <cuda_fp16.h>
#include <math.h>

#define NN 50000
#define EE 800000
#define DD 96
#define HIDN 128
#define OUTD 8
#define BN_EPS 1e-5f
#define AGG_EPS 1e-6f
#define NTILE 6250

// ---------------- device scratch ----------------
__device__ __align__(16) float g_h[NN * DD];
__device__ __align__(16) float g_A[NN * DD];
__device__ __align__(16) __half g_BDh[NN * DD * 2];  // B at [0,96), D at [96,192) per node
__device__ __align__(16) __half g_Eh[NN * DD];
__device__ __align__(16) float g_agg[NN * DD * 2];   // interleaved num/den
__device__ __align__(16) float g_hnew[NN * DD];
__device__ __align__(16) __half g_e[EE * DD];        // sorted order
__device__ __align__(16) __half g_enew[EE * DD];     // sorted order
__device__ __align__(16) float g_sums[4 * DD];
__device__ __align__(16) float g_scale_e[DD], g_shift_e[DD];
__device__ __align__(16) float g_scale_h[DD], g_shift_h[DD];
__device__ __align__(16) __half g_Wf_hi[20 * DD * DD];
__device__ __align__(16) __half g_Wf_lo[20 * DD * DD];
// dst-sorted edge structure
__device__ int g_perm[EE];
__device__ int g_src_s[EE];
__device__ int g_dst_s[EE];
__device__ int g_off[NN];
__device__ int g_cursor[NN];

// ---------------- helpers ----------------
__device__ __forceinline__ unsigned pack_h2(float x, float y) {
    __half2 t = __floats2half2_rn(x, y);
    return *reinterpret_cast<unsigned*>(&t);
}

__device__ __forceinline__ float sigmoid_fast(float x) {
    float t;
    asm("tanh.approx.f32 %0, %1;" : "=f"(t) : "f"(0.5f * x));
    return fmaf(0.5f, t, 0.5f);
}

__device__ __forceinline__ void prefetchL2(const void* p) {
    asm volatile("prefetch.global.L2 [%0];" :: "l"(p));
}

__device__ __forceinline__ void mma_f16(float* c, const unsigned* a, unsigned b0, unsigned b1) {
    asm volatile(
        "mma.sync.aligned.m16n8k16.row.col.f32.f16.f16.f32 "
        "{%0,%1,%2,%3},{%4,%5,%6,%7},{%8,%9},{%0,%1,%2,%3};"
        : "+f"(c[0]), "+f"(c[1]), "+f"(c[2]), "+f"(c[3])
        : "r"(a[0]), "r"(a[1]), "r"(a[2]), "r"(a[3]), "r"(b0), "r"(b1));
}

// ---------------- fused: dst histogram + weight prep ----------------
struct WPtrs { const float *a, *b, *c, *d, *e; };

__global__ void k_histprep(const int* __restrict__ dst, WPtrs p) {
    int idx = blockIdx.x * blockDim.x + threadIdx.x;
    if (idx < EE) atomicAdd(&g_off[dst[idx]], 1);
    if (idx < 20 * DD * DD) {
        int m = idx / (DD * DD), r = idx % (DD * DD);
        int k = r / DD, n = r % DD;
        int type = m >> 2, layer = m & 3;
        const float* src = type == 0 ? p.a : type == 1 ? p.b : type == 2 ? p.c
                           : type == 3 ? p.d : p.e;
        float w = src[layer * DD * DD + k * DD + n];
        __half hi = __float2half(w);
        g_Wf_hi[m * DD * DD + n * DD + k] = hi;
        g_Wf_lo[m * DD * DD + n * DD + k] = __float2half(w - __half2float(hi));
    }
}

__global__ void k_scan() {
    __shared__ int ssum[1024];
    const int STRIP = (NN + 1023) / 1024;
    int t = threadIdx.x;
    int beg = t * STRIP, end = beg + STRIP;
    if (end > NN) end = NN;
    int s = 0;
    for (int i = beg; i < end; i++) s += g_off[i];
    ssum[t] = s;
    __syncthreads();
    for (int ofs = 1; ofs < 1024; ofs <<= 1) {
        int v = (t >= ofs) ? ssum[t - ofs] : 0;
        __syncthreads();
        ssum[t] += v;
        __syncthreads();
    }
    int carry = (t > 0) ? ssum[t - 1] : 0;
    for (int i = beg; i < end; i++) {
        int v = g_off[i];
        g_off[i] = carry;
        carry += v;
    }
}

// smem layout node (u32): Ah[128*50] Whi[96*52] Wlo[96*52]
#define N_A 0
#define N_WHI (128 * 50)
#define N_WLO (128 * 50 + 96 * 52)
#define NODE_U32 (128 * 50 + 2 * 96 * 52)   // 16384 u32 = 65536 B

// ---------------- fused node GEMM (+ scatter when fuse==2) ----------------
__global__ __launch_bounds__(256, 3) void k_node(const float* __restrict__ bA, const float* __restrict__ bB,
                                                 const float* __restrict__ bD, const float* __restrict__ bE,
                                                 int layer, int fuse,
                                                 const float* __restrict__ h1, const float* __restrict__ h2,
                                                 const float* __restrict__ z,
                                                 const float* __restrict__ Wh_emb,
                                                 const float* __restrict__ bh_emb,
                                                 const int* __restrict__ src_in,
                                                 const int* __restrict__ dst_in) {
    extern __shared__ unsigned sm[];
    unsigned* Ah = sm + N_A;
    unsigned* Whi = sm + N_WHI;
    unsigned* Wlo = sm + N_WLO;
    int tid = threadIdx.x;

    if (fuse == 2) {
        int e = blockIdx.x * 256 + tid;
        if (e < EE) {
            int d = dst_in[e];
            int p = g_off[d] + atomicAdd(&g_cursor[d], 1);
            g_perm[p] = e;
            g_src_s[p] = src_in[e];
            g_dst_s[p] = d;
        }
        if (blockIdx.x >= (NN + 127) / 128) return;
    }

    int m0 = blockIdx.x * 128;
    int rows_valid = NN - m0;
    if (rows_valid > 128) rows_valid = 128;

    if (fuse == 2) {
        float* Whf = (float*)(sm + N_WHI);
        for (int i = tid; i < 26 * 96; i += 256) Whf[i] = Wh_emb[i];
        __syncthreads();
        for (int i = tid; i < 128 * 24; i += 256) {
            int r = i / 24, c4 = i % 24;
            int row = m0 + r;
            float4 v = make_float4(0.f, 0.f, 0.f, 0.f);
            if (r < rows_valid) {
                float x[26];
                const float* p1 = h1 + row * 6;
#pragma unroll
                for (int k = 0; k < 6; k++) x[k] = p1[k];
                const float* p2 = h2 + row * 4;
#pragma unroll
                for (int k = 0; k < 4; k++) x[6 + k] = p2[k];
                const float* p3 = z + row * 16;
#pragma unroll
                for (int k = 0; k < 16; k++) x[10 + k] = p3[k];
                float a[4];
#pragma unroll
                for (int c = 0; c < 4; c++) a[c] = bh_emb[c4 * 4 + c];
#pragma unroll
                for (int k = 0; k < 26; k++) {
#pragma unroll
                    for (int c = 0; c < 4; c++)
                        a[c] = fmaf(x[k], Whf[k * 96 + c4 * 4 + c], a[c]);
                }
                v = make_float4(a[0], a[1], a[2], a[3]);
                ((float4*)g_h)[(long long)row * 24 + c4] = v;
            }
            Ah[r * 50 + c4 * 2] = pack_h2(v.x, v.y);
            Ah[r * 50 + c4 * 2 + 1] = pack_h2(v.z, v.w);
        }
    } else {
        for (int i = tid; i < 128 * 24; i += 256) {
            int r = i / 24, c4 = i % 24;
            float4 v = make_float4(0.f, 0.f, 0.f, 0.f);
            if (r < rows_valid) {
                long long gi = (long long)(m0 + r) * 24 + c4;
                v = ((const float4*)g_h)[gi];
                float4 en = ((const float4*)g_hnew)[gi];
                int c = c4 * 4;
                v.x += fmaxf(0.f, en.x * g_scale_h[c] + g_shift_h[c]);
                v.y += fmaxf(0.f, en.y * g_scale_h[c + 1] + g_shift_h[c + 1]);
                v.z += fmaxf(0.f, en.z * g_scale_h[c + 2] + g_shift_h[c + 2]);
                v.w += fmaxf(0.f, en.w * g_scale_h[c + 3] + g_shift_h[c + 3]);
                ((float4*)g_h)[gi] = v;
            }
            Ah[r * 50 + c4 * 2] = pack_h2(v.x, v.y);
            Ah[r * 50 + c4 * 2 + 1] = pack_h2(v.z, v.w);
        }
    }

    int w = tid >> 5, lane = tid & 31;
    int wm = w & 3, wn = w >> 2;
    const int types[4] = {0, 1, 3, 4};
    const float* biases[4] = {bA, bB, bD, bE};

    for (int t = 0; t < 4; t++) {
        __syncthreads();
        const unsigned* gwh = (const unsigned*)(g_Wf_hi + (types[t] * 4 + layer) * DD * DD);
        const unsigned* gwl = (const unsigned*)(g_Wf_lo + (types[t] * 4 + layer) * DD * DD);
        for (int i = tid; i < 96 * 48; i += 256) {
            int n = i / 48, kp = i % 48;
            Whi[n * 52 + kp] = gwh[i];
            Wlo[n * 52 + kp] = gwl[i];
        }
        __syncthreads();

        float acc[2][6][4];
#pragma unroll
        for (int m = 0; m < 2; m++)
#pragma unroll
            for (int n = 0; n < 6; n++)
#pragma unroll
                for (int j = 0; j < 4; j++) acc[m][n][j] = 0.f;

#pragma unroll
        for (int kt = 0; kt < 6; kt++) {
            int kp = kt * 8 + (lane & 3);
            unsigned ah[2][4];
#pragma unroll
            for (int m = 0; m < 2; m++) {
                int row = wm * 32 + m * 16 + (lane >> 2);
                ah[m][0] = Ah[row * 50 + kp];
                ah[m][1] = Ah[(row + 8) * 50 + kp];
                ah[m][2] = Ah[row * 50 + kp + 4];
                ah[m][3] = Ah[(row + 8) * 50 + kp + 4];
            }
#pragma unroll
            for (int n = 0; n < 6; n++) {
                int col = wn * 48 + n * 8 + (lane >> 2);
                unsigned bh0 = Whi[col * 52 + kp], bh1 = Whi[col * 52 + kp + 4];
                unsigned bl0 = Wlo[col * 52 + kp], bl1 = Wlo[col * 52 + kp + 4];
#pragma unroll
                for (int m = 0; m < 2; m++) {
                    mma_f16(acc[m][n], ah[m], bh0, bh1);
                    mma_f16(acc[m][n], ah[m], bl0, bl1);
                }
            }
        }

        const float* bias = biases[t];
#pragma unroll
        for (int m = 0; m < 2; m++) {
#pragma unroll
            for (int n = 0; n < 6; n++) {
                int row = m0 + wm * 32 + m * 16 + (lane >> 2);
                int col = wn * 48 + n * 8 + ((lane & 3) << 1);
                float b0 = bias[col], b1 = bias[col + 1];
                float v00 = acc[m][n][0] + b0, v01 = acc[m][n][1] + b1;
                float v10 = acc[m][n][2] + b0, v11 = acc[m][n][3] + b1;
                if (t == 0) {
                    if (row < NN)
                        *(float2*)&g_A[(long long)row * 96 + col] = make_float2(v00, v01);
                    if (row + 8 < NN)
                        *(float2*)&g_A[(long long)(row + 8) * 96 + col] = make_float2(v10, v11);
                } else if (t < 3) {
                    int ofs = (t == 1) ? 0 : 96;
                    if (row < NN)
                        *(__half2*)&g_BDh[(long long)row * 192 + ofs + col] = __floats2half2_rn(v00, v01);
                    if (row + 8 < NN)
                        *(__half2*)&g_BDh[(long long)(row + 8) * 192 + ofs + col] = __floats2half2_rn(v10, v11);
                } else {
                    if (row < NN)
                        *(__half2*)&g_Eh[(long long)row * 96 + col] = __floats2half2_rn(v00, v01);
                    if (row + 8 < NN)
                        *(__half2*)&g_Eh[(long long)(row + 8) * 96 + col] = __floats2half2_rn(v10, v11);
                }
            }
        }
    }
}

// smem layout edge (u32): Whi[96*52] Wemb[384] | Ah/Sst[128*50] Sbd[128*100]
#define EW_HI 0
#define EW_EMB (96 * 52)
#define ER_OFF (96 * 52 + 384)          // 5376
#define ESBD_OFF (ER_OFF + 6400)        // 11776
#define EDGE_U32 (ESBD_OFF + 12800)     // 24576 u32 = 98304 B

// ---------------- persistent fused edge layer (384 threads, coalesced BD gather) ----------------
__global__ __launch_bounds__(384, 2) void k_edge(const __half* __restrict__ Whi_g,
                                                 const float* __restrict__ bC,
                                                 const float* __restrict__ efeat,
                                                 const float* __restrict__ We,
                                                 const float* __restrict__ be,
                                                 int fuse, int last) {
    extern __shared__ unsigned sm[];
    unsigned* Whi = sm + EW_HI;
    float* Wemb = (float*)(sm + EW_EMB);
    unsigned* Ah = sm + ER_OFF;              // aliases Sst
    __half* Sst = (__half*)(sm + ER_OFF);    // 128x100 halves (vv)
    unsigned* SbdU = sm + ESBD_OFF;          // 128 x 100 u32: B halves [0,96), D halves [96,192)
    __half* SbdH = (__half*)(sm + ESBD_OFF);
    __shared__ int s_src[128], s_dst[128];
    int tid = threadIdx.x;

    {
        const unsigned* gwh = (const unsigned*)Whi_g;
        for (int i = tid; i < 96 * 48; i += 384) {
            int n = i / 48, kp = i % 48;
            Whi[n * 52 + kp] = gwh[i];
        }
        if (fuse == 0 && tid < 384) Wemb[tid] = We[tid];
    }

    int w = tid >> 5, lane = tid & 31;
    int wm = w & 3, wn = w >> 2;              // 4 x 3 warp grid
    int colPair = (tid % 48) * 2, gP2 = tid / 48;  // pass-2: 8 groups x 16 rows
    float bs0 = 0.f, bs1 = 0.f, bq0 = 0.f, bq1 = 0.f;

    float bcr[8];
#pragma unroll
    for (int n = 0; n < 4; n++) {
        int col = wn * 32 + n * 8 + ((lane & 3) << 1);
        bcr[2 * n] = bC[col];
        bcr[2 * n + 1] = bC[col + 1];
    }

    for (int tile = blockIdx.x; tile < NTILE; tile += gridDim.x) {
        int e0 = tile * 128;
        __syncthreads();
        if (tid < 128) {
            s_src[tid] = g_src_s[e0 + tid];
            s_dst[tid] = g_dst_s[e0 + tid];
        }

        // coalesced B+D gather: 24 consecutive lanes cover one edge's 384 B
#pragma unroll
        for (int idx = tid; idx < 128 * 24; idx += 384) {
            int e = idx / 24, u = idx % 24;
            int s = g_src_s[e0 + e];
            uint4 v = *((const uint4*)(g_BDh + (long long)s * 192) + u);
            unsigned* pb = SbdU + e * 100 + u * 4;
            pb[0] = v.x; pb[1] = v.y; pb[2] = v.z; pb[3] = v.w;
        }

        if (fuse == 0) {
            for (int i = tid; i < 128 * 12; i += 384) {
                int r = i / 12, c8 = i % 12;
                int er = e0 + r;
                const float4 ef = ((const float4*)efeat)[g_perm[er]];
                uint4 v;
                __half2* vh = (__half2*)&v;
#pragma unroll
                for (int j = 0; j < 4; j++) {
                    int c = c8 * 8 + 2 * j;
                    float o0 = be[c] + ef.x * Wemb[c] + ef.y * Wemb[96 + c] +
                               ef.z * Wemb[192 + c] + ef.w * Wemb[288 + c];
                    float o1 = be[c + 1] + ef.x * Wemb[c + 1] + ef.y * Wemb[96 + c + 1] +
                               ef.z * Wemb[192 + c + 1] + ef.w * Wemb[288 + c + 1];
                    vh[j] = __floats2half2_rn(o0, o1);
                }
                __stcs((uint4*)g_e + (long long)er * 12 + c8, v);
                unsigned* vu = (unsigned*)&v;
#pragma unroll
                for (int j = 0; j < 4; j++) Ah[r * 50 + c8 * 4 + j] = vu[j];
            }
        } else {
            for (int i = tid; i < 128 * 12; i += 384) {
                int r = i / 12, c8 = i % 12;
                long long gi = (long long)(e0 + r) * 12 + c8;
                uint4 v = __ldcs((const uint4*)g_e + gi);
                uint4 en = __ldcs((const uint4*)g_enew + gi);
                __half2* vh = (__half2*)&v;
                __half2* eh = (__half2*)&en;
                int c = c8 * 8;
#pragma unroll
                for (int j = 0; j < 4; j++) {
                    float2 f = __half22float2(vh[j]);
                    float2 ev = __half22float2(eh[j]);
                    f.x += fmaxf(0.f, ev.x * g_scale_e[c + 2 * j] + g_shift_e[c + 2 * j]);
                    f.y += fmaxf(0.f, ev.y * g_scale_e[c + 2 * j + 1] + g_shift_e[c + 2 * j + 1]);
                    vh[j] = __floats2half2_rn(f.x, f.y);
                }
                if (!last) __stcs((uint4*)g_e + gi, v);
                unsigned* vu = (unsigned*)&v;
#pragma unroll
                for (int j = 0; j < 4; j++) Ah[r * 50 + c8 * 4 + j] = vu[j];
            }
        }

        // L2 prefetch for tile + gridDim
        {
            int nt = tile + gridDim.x;
            if (nt < NTILE) {
                int ne0 = nt * 128;
                if (fuse != 0) {
                    const char* eb = (const char*)(g_e + (long long)ne0 * 96);
                    const char* nb = (const char*)(g_enew + (long long)ne0 * 96);
                    const char* p = (tid < 192) ? eb + tid * 128 : nb + (tid - 192) * 128;
                    prefetchL2(p);
                }
                if (tid < 128) {
                    int s = g_src_s[ne0 + tid], d = g_dst_s[ne0 + tid];
                    const char* pb = (const char*)(g_BDh + (long long)s * 192);
                    const char* pe = (const char*)(g_Eh + (long long)d * 96);
                    prefetchL2(pb); prefetchL2(pb + 128); prefetchL2(pb + 256);
                    prefetchL2(pe); prefetchL2(pe + 184);
                }
            }
        }
        __syncthreads();

        // fp16 GEMM: Ce = e @ Whi
        float acc[2][4][4];
#pragma unroll
        for (int m = 0; m < 2; m++)
#pragma unroll
            for (int n = 0; n < 4; n++)
#pragma unroll
                for (int j = 0; j < 4; j++) acc[m][n][j] = 0.f;

#pragma unroll
        for (int kt = 0; kt < 6; kt++) {
            int kp = kt * 8 + (lane & 3);
            unsigned ah[2][4];
#pragma unroll
            for (int m = 0; m < 2; m++) {
                int row = wm * 32 + m * 16 + (lane >> 2);
                ah[m][0] = Ah[row * 50 + kp];
                ah[m][1] = Ah[(row + 8) * 50 + kp];
                ah[m][2] = Ah[row * 50 + kp + 4];
                ah[m][3] = Ah[(row + 8) * 50 + kp + 4];
            }
#pragma unroll
            for (int n = 0; n < 4; n++) {
                int col = wn * 32 + n * 8 + (lane >> 2);
                unsigned bh0 = Whi[col * 52 + kp], bh1 = Whi[col * 52 + kp + 4];
#pragma unroll
                for (int m = 0; m < 2; m++)
                    mma_f16(acc[m][n], ah[m], bh0, bh1);
            }
        }
        __syncthreads();  // all warps done reading Ah

        // fused epilogue: vv = acc + bC + D(smem) + E[dst](global, dst-sorted => coalesced)
#pragma unroll
        for (int m = 0; m < 2; m++) {
            int lr0 = wm * 32 + m * 16 + (lane >> 2);
            int lr1 = lr0 + 8;
            int d0 = s_dst[lr0], d1 = s_dst[lr1];
            const __half* E0 = g_Eh + (long long)d0 * 96;
            const __half* E1 = g_Eh + (long long)d1 * 96;
#pragma unroll
            for (int n = 0; n < 4; n++) {
                int col = wn * 32 + n * 8 + ((lane & 3) << 1);
                float2 dv0 = __half22float2(*(const __half2*)&SbdH[lr0 * 200 + 96 + col]);
                float2 dv1 = __half22float2(*(const __half2*)&SbdH[lr1 * 200 + 96 + col]);
                float2 ev0 = __half22float2(*(const __half2*)&E0[col]);
                float2 ev1 = __half22float2(*(const __half2*)&E1[col]);
                float v00 = acc[m][n][0] + bcr[2 * n] + dv0.x + ev0.x;
                float v01 = acc[m][n][1] + bcr[2 * n + 1] + dv0.y + ev0.y;
                float v10 = acc[m][n][2] + bcr[2 * n] + dv1.x + ev1.x;
                float v11 = acc[m][n][3] + bcr[2 * n + 1] + dv1.y + ev1.y;
                __half2 o0 = __floats2half2_rn(v00, v01);
                __half2 o1 = __floats2half2_rn(v10, v11);
                *(__half2*)&Sst[lr0 * 100 + col] = o0;
                *(__half2*)&Sst[lr1 * 100 + col] = o1;
                if (!last) {
                    __stcs((__half2*)&g_enew[(long long)(e0 + lr0) * 96 + col], o0);
                    __stcs((__half2*)&g_enew[(long long)(e0 + lr1) * 96 + col], o1);
                }
            }
        }
        __syncthreads();

        // pass 2: per-column-pair segment scan, 8 groups x 16 rows
        {
            int rbeg = gP2 * 16, rend = rbeg + 16;
            float n0 = 0.f, n1 = 0.f, de0 = 0.f, de1 = 0.f;
            int d = s_dst[rbeg];
            for (int r = rbeg; r < rend; r++) {
                float2 vv = __half22float2(*(const __half2*)&Sst[r * 100 + colPair]);
                float2 bv = __half22float2(*(const __half2*)&SbdH[r * 200 + colPair]);
                float sg0 = sigmoid_fast(vv.x);
                float sg1 = sigmoid_fast(vv.y);
                n0 = fmaf(sg0, bv.x, n0);
                n1 = fmaf(sg1, bv.y, n1);
                de0 += sg0;
                de1 += sg1;
                bs0 += vv.x; bs1 += vv.y;
                bq0 = fmaf(vv.x, vv.x, bq0);
                bq1 = fmaf(vv.y, vv.y, bq1);
                int dn = (r + 1 < rend) ? s_dst[r + 1] : -1;
                if (dn != d) {
                    atomicAdd((float4*)&g_agg[((long long)d * 96 + colPair) * 2],
                              make_float4(n0, de0, n1, de1));
                    n0 = 0.f; n1 = 0.f; de0 = 0.f; de1 = 0.f;
                    d = dn;
                }
            }
        }
    }
    if (!last) {
        atomicAdd(&g_sums[colPair], bs0);
        atomicAdd(&g_sums[colPair + 1], bs1);
        atomicAdd(&g_sums[DD + colPair], bq0);
        atomicAdd(&g_sums[DD + colPair + 1], bq1);
    }
}

// ---------------- h_new + BN-h moments + re-zero agg; block 0 also finalizes BN-e ----------------
__global__ __launch_bounds__(384) void k_hnew(int do_e, const float* __restrict__ eg,
                                              const float* __restrict__ eb) {
    __shared__ float ssum[96], ssq[96];
    int tid = threadIdx.x;
    int col = tid % 96, yr = tid / 96;
    if (blockIdx.x == 0 && do_e && tid < 96) {
        float mu = g_sums[tid] * (1.f / EE);
        float var = g_sums[DD + tid] * (1.f / EE) - mu * mu;
        float rstd = rsqrtf(var + BN_EPS);
        float sc = eg[tid] * rstd;
        g_scale_e[tid] = sc;
        g_shift_e[tid] = eb[tid] - mu * sc;
        g_sums[tid] = 0.f;
        g_sums[DD + tid] = 0.f;
    }
    if (tid < 96) { ssum[tid] = 0.f; ssq[tid] = 0.f; }
    __syncthreads();
    float sm = 0.f, sq = 0.f;
    for (int row = blockIdx.x * 4 + yr; row < NN; row += gridDim.x * 4) {
        int i = row * 96 + col;
        float2 nd = ((float2*)g_agg)[i];
        float v = g_A[i] + nd.x / (nd.y + AGG_EPS);
        g_hnew[i] = v;
        ((float2*)g_agg)[i] = make_float2(0.f, 0.f);
        sm += v;
        sq = fmaf(v, v, sq);
    }
    atomicAdd(&ssum[col], sm);
    atomicAdd(&ssq[col], sq);
    __syncthreads();
    if (tid < 96) {
        atomicAdd(&g_sums[2 * DD + tid], ssum[tid]);
        atomicAdd(&g_sums[3 * DD + tid], ssq[tid]);
    }
}

// ---------------- finalize BN-h stats ----------------
__global__ void k_finalize(const float* __restrict__ g, const float* __restrict__ b) {
    int c = threadIdx.x;
    if (c >= 96) return;
    float mu = g_sums[2 * DD + c] * (1.f / NN);
    float var = g_sums[3 * DD + c] * (1.f / NN) - mu * mu;
    float rstd = rsqrtf(var + BN_EPS);
    float sc = g[c] * rstd;
    g_scale_h[c] = sc;
    g_shift_h[c] = b[c] - mu * sc;
    g_sums[2 * DD + c] = 0.f;
    g_sums[3 * DD + c] = 0.f;
}

// ---------------- MLP head (re-zeroes sort scratch for next replay) ----------------
__global__ __launch_bounds__(128) void k_head(const float* __restrict__ W1,
                                              const float* __restrict__ b1,
                                              const float* __restrict__ W2,
                                              const float* __restrict__ b2,
                                              const float* __restrict__ maxa,
                                              float* __restrict__ out) {
    __shared__ float hs[8][96];
    __shared__ float hid[8][HIDN];
    int r0 = blockIdx.x * 8;
    int tid = threadIdx.x;
    int gid = blockIdx.x * 128 + tid;
    if (gid < NN) { g_off[gid] = 0; g_cursor[gid] = 0; }
    for (int i = tid; i < 8 * 96; i += 128) {
        int r = i / 96, c = i % 96;
        int row = r0 + r;
        float v = 0.f;
        if (row < NN) {
            long long gi = (long long)row * 96 + c;
            v = g_h[gi] + fmaxf(0.f, g_hnew[gi] * g_scale_h[c] + g_shift_h[c]);
        }
        hs[r][c] = v;
    }
    __syncthreads();
    float acc[8];
#pragma unroll
    for (int r = 0; r < 8; r++) acc[r] = b1[tid];
#pragma unroll 4
    for (int k = 0; k < 96; k++) {
        float w = W1[k * HIDN + tid];
#pragma unroll
        for (int r = 0; r < 8; r++) acc[r] += hs[r][k] * w;
    }
#pragma unroll
    for (int r = 0; r < 8; r++) hid[r][tid] = fmaxf(acc[r], 0.f);
    __syncthreads();
    if (tid < 64) {
        int r = tid >> 3, c = tid & 7;
        int row = r0 + r;
        if (row < NN) {
            float a = b2[c];
#pragma unroll 8
            for (int k = 0; k < HIDN; k++) a += hid[r][k] * W2[k * OUTD + c];
            out[(long long)row * OUTD + c] = maxa[row] * tanhf(a);
        }
    }
}

// ---------------- launch ----------------
extern "C" void kernel_launch(void* const* d_in, const int* in_sizes, int n_in,
                              void* d_out, int out_size) {
    const float* h1 = (const float*)d_in[0];
    const float* h2 = (const float*)d_in[1];
    const float* z = (const float*)d_in[2];
    const float* efeat = (const float*)d_in[3];
    const float* max_action = (const float*)d_in[4];
    const float* Wh_emb = (const float*)d_in[5];
    const float* bh_emb = (const float*)d_in[6];
    const float* We_emb = (const float*)d_in[7];
    const float* be_emb = (const float*)d_in[8];
    const float* WA = (const float*)d_in[9];
    const float* bA = (const float*)d_in[10];
    const float* WB = (const float*)d_in[11];
    const float* bB = (const float*)d_in[12];
    const float* WC = (const float*)d_in[13];
    const float* bC = (const float*)d_in[14];
    const float* WD = (const float*)d_in[15];
    const float* bD = (const float*)d_in[16];
    const float* WE = (const float*)d_in[17];
    const float* bE = (const float*)d_in[18];
    const float* bn_h_g = (const float*)d_in[19];
    const float* bn_h_b = (const float*)d_in[20];
    const float* bn_e_g = (const float*)d_in[21];
    const float* bn_e_b = (const float*)d_in[22];
    const float* W1 = (const float*)d_in[23];
    const float* b1 = (const float*)d_in[24];
    const float* W2 = (const float*)d_in[25];
    const float* b2 = (const float*)d_in[26];
    const int* src = (const int*)d_in[27];
    const int* dst = (const int*)d_in[28];
    float* out = (float*)d_out;

    __half* p_wfhi;
    cudaGetSymbolAddress((void**)&p_wfhi, g_Wf_hi);

    const int smem_node = NODE_U32 * 4;  // 65536
    const int smem_edge = EDGE_U32 * 4;  // 98304
    cudaFuncSetAttribute(k_node, cudaFuncAttributeMaxDynamicSharedMemorySize, smem_node);
    cudaFuncSetAttribute(k_edge, cudaFuncAttributeMaxDynamicSharedMemorySize, smem_edge);

    WPtrs wp{WA, WB, WC, WD, WE};
    k_histprep<<<(EE + 255) / 256, 256>>>(dst, wp);
    k_scan<<<1, 1024>>>();

    const int nblk = (NN + 127) / 128;  // 391
    const int sblk = (EE + 255) / 256;  // 3125
    const int eblk = 296;

    for (int l = 0; l < 4; l++) {
        k_node<<<(l == 0 ? sblk : nblk), 256, smem_node>>>(
            bA + l * DD, bB + l * DD, bD + l * DD, bE + l * DD,
            l, l == 0 ? 2 : 1, h1, h2, z, Wh_emb, bh_emb, src, dst);
        k_edge<<<eblk, 384, smem_edge>>>(p_wfhi + (2 * 4 + l) * DD * DD,
                                         bC + l * DD, efeat, We_emb, be_emb,
                                         l == 0 ? 0 : 1, l == 3 ? 1 : 0);
        k_hnew<<<256, 384>>>(l < 3 ? 1 : 0, bn_e_g + l * DD, bn_e_b + l * DD);
        k_finalize<<<1, 96>>>(bn_h_g + l * DD, bn_h_b + l * DD);
    }

    k_head<<<NN / 8, 128>>>(W1, b1, W2, b2, max_action, out);
}